// round 1
// baseline (speedup 1.0000x reference)
#include <cuda_runtime.h>
#include <cstdint>

// Problem constants
#define BB 4
#define TT 2048
#define DD 1024
#define HH 16
#define DKK 64
#define SCALE_ 0.125f      // 1/sqrt(64)
#define EPS_LN_ 1e-5f
#define EPS_NORM_ 1e-8f

// ---------------- scratch (static __device__, no allocation) ----------------
__device__ float g_xn[BB * TT * DD];            // layernormed input [B,T,D]
__device__ float g_q[BB * HH * TT * DKK];       // [B,H,T,DK]
__device__ float g_k[BB * HH * TT * DKK];
__device__ float g_v[BB * HH * TT * DKK];
__device__ float g_ao[BB * TT * DD];            // attention output [B,T,D]
__device__ unsigned char g_cmask[BB * TT];      // canonical mask (1 = masked)
__device__ int g_flags[3];                      // mask dtype detection flags

// ---------------- mask dtype detection ----------------
// jax bool input may arrive as bool (1B), int32, or float32. Scan the first
// 8192 bytes (valid under all three layouts) and classify by byte pattern.
__global__ void detect_mask_kernel(const unsigned char* __restrict__ m) {
    if (threadIdx.x == 0) { g_flags[0] = 0; g_flags[1] = 0; g_flags[2] = 0; }
    __syncthreads();
    int a = 0, bhi = 0, c = 0;
    for (int i = threadIdx.x; i < BB * TT; i += blockDim.x) {
        unsigned char v = m[i];
        if (v) {
            int r = i & 3;
            if (r == 0) a = 1;
            else if (r == 1) c = 1;
            else bhi = 1;   // residues 2,3 (float32 1.0f has bytes 0x80,0x3F here)
        }
    }
    if (a)   atomicOr(&g_flags[0], 1);
    if (bhi) atomicOr(&g_flags[1], 1);
    if (c)   atomicOr(&g_flags[2], 1);
}

__global__ void convert_mask_kernel(const void* __restrict__ m) {
    int i = blockIdx.x * blockDim.x + threadIdx.x;
    if (i >= BB * TT) return;
    int A = g_flags[0], Bf = g_flags[1], C = g_flags[2];
    unsigned char out;
    if (A && !Bf && !C) {
        out = (((const int*)m)[i] != 0);            // int32 0/1
    } else if (!A && Bf) {
        out = (((const float*)m)[i] != 0.0f);       // float32 0.0/1.0
    } else {
        out = (((const unsigned char*)m)[i] != 0);  // bool / uint8 (default, safe)
    }
    g_cmask[i] = out;
}

// ---------------- LayerNorm ----------------
__global__ __launch_bounds__(256) void ln_kernel(
    const float* __restrict__ x, const float* __restrict__ g,
    const float* __restrict__ b) {
    __shared__ float red_s[8], red_ss[8];
    int row = blockIdx.x;                 // 0..8191
    int tid = threadIdx.x;                // 256 threads, 4 elems each
    const float* xr = x + (size_t)row * DD;
    float4 xv = *(const float4*)&xr[tid * 4];
    float s  = xv.x + xv.y + xv.z + xv.w;
    float ss = xv.x*xv.x + xv.y*xv.y + xv.z*xv.z + xv.w*xv.w;
    #pragma unroll
    for (int o = 16; o > 0; o >>= 1) {
        s  += __shfl_xor_sync(~0u, s, o);
        ss += __shfl_xor_sync(~0u, ss, o);
    }
    int warp = tid >> 5, lane = tid & 31;
    if (lane == 0) { red_s[warp] = s; red_ss[warp] = ss; }
    __syncthreads();
    if (warp == 0) {
        s  = (lane < 8) ? red_s[lane]  : 0.f;
        ss = (lane < 8) ? red_ss[lane] : 0.f;
        #pragma unroll
        for (int o = 4; o > 0; o >>= 1) {
            s  += __shfl_xor_sync(~0u, s, o);
            ss += __shfl_xor_sync(~0u, ss, o);
        }
        if (lane == 0) { red_s[0] = s; red_ss[0] = ss; }
    }
    __syncthreads();
    float mu  = red_s[0] * (1.0f / DD);
    float var = red_ss[0] * (1.0f / DD) - mu * mu;
    float inv = rsqrtf(var + EPS_LN_);
    float4 gv = *(const float4*)&g[tid * 4];
    float4 bv = *(const float4*)&b[tid * 4];
    float4 yv;
    yv.x = (xv.x - mu) * inv * gv.x + bv.x;
    yv.y = (xv.y - mu) * inv * gv.y + bv.y;
    yv.z = (xv.z - mu) * inv * gv.z + bv.z;
    yv.w = (xv.w - mu) * inv * gv.w + bv.w;
    *(float4*)&g_xn[(size_t)row * DD + tid * 4] = yv;
}

// ---------------- SIMT fp32 GEMM: C = A @ W^T + bias ----------------
// A [8192,1024] row-major, W [1024,1024] row-major (row e dotted with x).
// mode 0/1/2: A=g_xn, C = g_q/g_k/g_v in [B,H,T,DK] layout.
// mode 3:     A=g_ao, C = dout [B,T,D], fused *0.5.
#define GM 128
#define GN 128
#define GK 8
__global__ __launch_bounds__(256) void gemm_kernel(
    const float* __restrict__ W, const float* __restrict__ bias,
    int mode, float* __restrict__ dout) {
    __shared__ float As[GK][GM];
    __shared__ float Bs[GK][GN];
    const float* Aptr = (mode < 3) ? g_xn : g_ao;
    int tid = threadIdx.x;
    int m0 = blockIdx.y * GM;
    int n0 = blockIdx.x * GN;
    int arow = tid >> 1;           // 0..127
    int ak4  = (tid & 1) * 4;      // 0 or 4
    int ty = tid >> 4, tx = tid & 15;
    float acc[8][8];
    #pragma unroll
    for (int i = 0; i < 8; i++)
        #pragma unroll
        for (int j = 0; j < 8; j++) acc[i][j] = 0.f;

    for (int k0 = 0; k0 < DD; k0 += GK) {
        float4 av = *(const float4*)&Aptr[(size_t)(m0 + arow) * DD + k0 + ak4];
        float4 bv = *(const float4*)&W[(size_t)(n0 + arow) * DD + k0 + ak4];
        __syncthreads();
        As[ak4+0][arow] = av.x; As[ak4+1][arow] = av.y;
        As[ak4+2][arow] = av.z; As[ak4+3][arow] = av.w;
        Bs[ak4+0][arow] = bv.x; Bs[ak4+1][arow] = bv.y;
        Bs[ak4+2][arow] = bv.z; Bs[ak4+3][arow] = bv.w;
        __syncthreads();
        #pragma unroll
        for (int kk = 0; kk < GK; kk++) {
            const float4* ap = (const float4*)&As[kk][ty * 8];
            const float4* bp = (const float4*)&Bs[kk][tx * 8];
            float4 a0 = ap[0], a1 = ap[1];
            float4 b0 = bp[0], b1 = bp[1];
            float a[8] = {a0.x,a0.y,a0.z,a0.w,a1.x,a1.y,a1.z,a1.w};
            float bvv[8] = {b0.x,b0.y,b0.z,b0.w,b1.x,b1.y,b1.z,b1.w};
            #pragma unroll
            for (int i = 0; i < 8; i++)
                #pragma unroll
                for (int j = 0; j < 8; j++)
                    acc[i][j] = fmaf(a[i], bvv[j], acc[i][j]);
        }
    }

    if (mode < 3) {
        float* C = (mode == 0) ? g_q : (mode == 1) ? g_k : g_v;
        #pragma unroll
        for (int i = 0; i < 8; i++) {
            int m = m0 + ty * 8 + i;
            int bi = m >> 11;             // /T
            int t  = m & (TT - 1);
            #pragma unroll
            for (int j = 0; j < 8; j++) {
                int e = n0 + tx * 8 + j;
                float v = acc[i][j] + bias[e];
                int h = e >> 6, dk = e & 63;
                C[((((size_t)bi * HH + h) * TT + t) << 6) + dk] = v;
            }
        }
    } else {
        #pragma unroll
        for (int i = 0; i < 8; i++) {
            int m = m0 + ty * 8 + i;
            #pragma unroll
            for (int j = 0; j < 8; j++) {
                int e = n0 + tx * 8 + j;
                dout[(size_t)m * DD + e] = (acc[i][j] + bias[e]) * 0.5f;
            }
        }
    }
}

// ---------------- L2 normalize rows of 64 (Q and K) ----------------
__global__ __launch_bounds__(256) void l2norm_kernel() {
    int warp = (blockIdx.x * blockDim.x + threadIdx.x) >> 5;  // 0..131071
    int lane = threadIdx.x & 31;
    float* base = (blockIdx.y == 0) ? g_q : g_k;
    float* p = base + (size_t)warp * DKK + lane * 2;
    float2 v = *(float2*)p;
    float ss = v.x * v.x + v.y * v.y;
    #pragma unroll
    for (int o = 16; o > 0; o >>= 1) ss += __shfl_xor_sync(~0u, ss, o);
    float n = sqrtf(ss);
    float inv = 1.0f / fmaxf(n, EPS_NORM_);
    v.x *= inv; v.y *= inv;
    *(float2*)p = v;
}

// ---------------- Flash-style attention ----------------
// grid (T/64, B*H), block 256. 4 threads per query; K/V tiles in smem.
__global__ __launch_bounds__(256) void attn_kernel() {
    __shared__ float Ks[64][64];
    __shared__ float Vs[64][64];
    __shared__ unsigned char Ms[64];
    int bh = blockIdx.y;            // b*H + h
    int bi = bh >> 4;               // /H
    int h  = bh & 15;
    int qt = blockIdx.x;
    int tid = threadIdx.x;
    int qi = tid >> 2;              // query in tile 0..63
    int l4 = tid & 3;               // dim-quarter 0..3

    const float* qbase = g_q + (((size_t)bh * TT + qt * 64 + qi) << 6) + l4 * 16;
    float q[16];
    #pragma unroll
    for (int i = 0; i < 16; i += 4) {
        float4 t = *(const float4*)(qbase + i);
        q[i] = t.x; q[i+1] = t.y; q[i+2] = t.z; q[i+3] = t.w;
    }
    float o[16];
    #pragma unroll
    for (int i = 0; i < 16; i++) o[i] = 0.f;
    float mmax = -1e30f, lsum = 0.f;

    const unsigned char* mrow = g_cmask + bi * TT;
    const float* kbase = g_k + (((size_t)bh * TT) << 6);
    const float* vbase = g_v + (((size_t)bh * TT) << 6);

    for (int kt = 0; kt < TT / 64; kt++) {
        __syncthreads();
        const float* kb = kbase + ((size_t)(kt * 64) << 6);
        const float* vb = vbase + ((size_t)(kt * 64) << 6);
        #pragma unroll
        for (int r = 0; r < 4; r++) {
            int f4 = tid + r * 256;             // 0..1023 float4 slots
            int row = f4 >> 4;
            int col = (f4 & 15) * 4;
            *(float4*)&Ks[row][col] = *(const float4*)&kb[row * 64 + col];
            *(float4*)&Vs[row][col] = *(const float4*)&vb[row * 64 + col];
        }
        if (tid < 64) Ms[tid] = mrow[kt * 64 + tid];
        __syncthreads();

        #pragma unroll 2
        for (int j = 0; j < 64; j++) {
            float p = 0.f;
            const float* kr = &Ks[j][l4 * 16];
            #pragma unroll
            for (int d = 0; d < 16; d++) p = fmaf(q[d], kr[d], p);
            p += __shfl_xor_sync(~0u, p, 1);
            p += __shfl_xor_sync(~0u, p, 2);
            float s = p * SCALE_;
            s = fminf(fmaxf(s, -10.f), 10.f);
            if (Ms[j]) s = -10000.f;
            if (s > mmax) {                   // lazy rescale
                float corr = __expf(mmax - s);
                lsum *= corr;
                #pragma unroll
                for (int d = 0; d < 16; d++) o[d] *= corr;
                mmax = s;
            }
            float w = __expf(s - mmax);
            lsum += w;
            const float* vr = &Vs[j][l4 * 16];
            #pragma unroll
            for (int d = 0; d < 16; d++) o[d] = fmaf(w, vr[d], o[d]);
        }
    }
    float inv = 1.0f / lsum;
    // write to g_ao [B,T,D], column block h*64 + l4*16
    float* ob = g_ao + ((size_t)bi * TT + qt * 64 + qi) * DD + h * 64 + l4 * 16;
    #pragma unroll
    for (int i = 0; i < 16; i += 4) {
        float4 t;
        t.x = o[i] * inv; t.y = o[i+1] * inv; t.z = o[i+2] * inv; t.w = o[i+3] * inv;
        *(float4*)(ob + i) = t;
    }
}

// ---------------- launch ----------------
extern "C" void kernel_launch(void* const* d_in, const int* in_sizes, int n_in,
                              void* d_out, int out_size) {
    const float* x    = (const float*)d_in[0];
    const void*  mask = d_in[1];
    const float* wq = (const float*)d_in[2];
    const float* bq = (const float*)d_in[3];
    const float* wk = (const float*)d_in[4];
    const float* bk = (const float*)d_in[5];
    const float* wv = (const float*)d_in[6];
    const float* bv = (const float*)d_in[7];
    const float* wo = (const float*)d_in[8];
    const float* bo = (const float*)d_in[9];
    const float* ln_g = (const float*)d_in[10];
    const float* ln_b = (const float*)d_in[11];
    float* out = (float*)d_out;

    detect_mask_kernel<<<1, 256>>>((const unsigned char*)mask);
    convert_mask_kernel<<<(BB * TT + 255) / 256, 256>>>(mask);
    ln_kernel<<<BB * TT, 256>>>(x, ln_g, ln_b);

    dim3 ggrid(DD / GN, (BB * TT) / GM);
    gemm_kernel<<<ggrid, 256>>>(wq, bq, 0, nullptr);
    gemm_kernel<<<ggrid, 256>>>(wk, bk, 1, nullptr);
    gemm_kernel<<<ggrid, 256>>>(wv, bv, 2, nullptr);

    dim3 l2grid((BB * HH * TT) / 8, 2);   // 8 warps (rows) per 256-thread block
    l2norm_kernel<<<l2grid, 256>>>();

    dim3 agrid(TT / 64, BB * HH);
    attn_kernel<<<agrid, 256>>>();

    gemm_kernel<<<ggrid, 256>>>(wo, bo, 3, out);
}

// round 2
// speedup vs baseline: 6.6283x; 6.6283x over previous
#include <cuda_runtime.h>
#include <cstdint>

// Problem constants
#define BB 4
#define TT 2048
#define DD 1024
#define HH 16
#define DKK 64
#define SCALE_ 0.125f      // 1/sqrt(64)
#define EPS_LN_ 1e-5f
#define EPS_NORM_ 1e-8f

// ---------------- scratch (static __device__, no allocation) ----------------
__device__ float g_xn[BB * TT * DD];            // layernormed input [B,T,D]
__device__ float g_q[BB * HH * TT * DKK];       // [B,H,T,DK]
__device__ float g_k[BB * HH * TT * DKK];
__device__ float g_v[BB * HH * TT * DKK];
__device__ float g_ao[BB * TT * DD];            // attention output [B,T,D]
__device__ unsigned char g_cmask[BB * TT];      // canonical mask (1 = masked)
__device__ int g_flags[3];                      // mask dtype detection flags

// ---------------- tf32 helpers ----------------
__device__ __forceinline__ unsigned f2tf(float x) {
    unsigned r;
    asm("cvt.rna.tf32.f32 %0, %1;" : "=r"(r) : "f"(x));
    return r;
}
__device__ __forceinline__ void mma_tf32(float* d, const unsigned* a,
                                         const unsigned* b, const float* c) {
    asm volatile(
        "mma.sync.aligned.m16n8k8.row.col.f32.tf32.tf32.f32 "
        "{%0,%1,%2,%3}, {%4,%5,%6,%7}, {%8,%9}, {%10,%11,%12,%13};"
        : "=f"(d[0]), "=f"(d[1]), "=f"(d[2]), "=f"(d[3])
        : "r"(a[0]), "r"(a[1]), "r"(a[2]), "r"(a[3]),
          "r"(b[0]), "r"(b[1]),
          "f"(c[0]), "f"(c[1]), "f"(c[2]), "f"(c[3]));
}

// ---------------- mask dtype detection ----------------
__global__ void detect_mask_kernel(const unsigned char* __restrict__ m) {
    if (threadIdx.x == 0) { g_flags[0] = 0; g_flags[1] = 0; g_flags[2] = 0; }
    __syncthreads();
    int a = 0, bhi = 0, c = 0;
    for (int i = threadIdx.x; i < BB * TT; i += blockDim.x) {
        unsigned char v = m[i];
        if (v) {
            int r = i & 3;
            if (r == 0) a = 1;
            else if (r == 1) c = 1;
            else bhi = 1;
        }
    }
    if (a)   atomicOr(&g_flags[0], 1);
    if (bhi) atomicOr(&g_flags[1], 1);
    if (c)   atomicOr(&g_flags[2], 1);
}

__global__ void convert_mask_kernel(const void* __restrict__ m) {
    int i = blockIdx.x * blockDim.x + threadIdx.x;
    if (i >= BB * TT) return;
    int A = g_flags[0], Bf = g_flags[1], C = g_flags[2];
    unsigned char out;
    if (A && !Bf && !C) {
        out = (((const int*)m)[i] != 0);
    } else if (!A && Bf) {
        out = (((const float*)m)[i] != 0.0f);
    } else {
        out = (((const unsigned char*)m)[i] != 0);
    }
    g_cmask[i] = out;
}

// ---------------- LayerNorm ----------------
__global__ __launch_bounds__(256) void ln_kernel(
    const float* __restrict__ x, const float* __restrict__ g,
    const float* __restrict__ b) {
    __shared__ float red_s[8], red_ss[8];
    int row = blockIdx.x;
    int tid = threadIdx.x;
    const float* xr = x + (size_t)row * DD;
    float4 xv = *(const float4*)&xr[tid * 4];
    float s  = xv.x + xv.y + xv.z + xv.w;
    float ss = xv.x*xv.x + xv.y*xv.y + xv.z*xv.z + xv.w*xv.w;
    #pragma unroll
    for (int o = 16; o > 0; o >>= 1) {
        s  += __shfl_xor_sync(~0u, s, o);
        ss += __shfl_xor_sync(~0u, ss, o);
    }
    int warp = tid >> 5, lane = tid & 31;
    if (lane == 0) { red_s[warp] = s; red_ss[warp] = ss; }
    __syncthreads();
    if (warp == 0) {
        s  = (lane < 8) ? red_s[lane]  : 0.f;
        ss = (lane < 8) ? red_ss[lane] : 0.f;
        #pragma unroll
        for (int o = 4; o > 0; o >>= 1) {
            s  += __shfl_xor_sync(~0u, s, o);
            ss += __shfl_xor_sync(~0u, ss, o);
        }
        if (lane == 0) { red_s[0] = s; red_ss[0] = ss; }
    }
    __syncthreads();
    float mu  = red_s[0] * (1.0f / DD);
    float var = red_ss[0] * (1.0f / DD) - mu * mu;
    float inv = rsqrtf(var + EPS_LN_);
    float4 gv = *(const float4*)&g[tid * 4];
    float4 bv = *(const float4*)&b[tid * 4];
    float4 yv;
    yv.x = (xv.x - mu) * inv * gv.x + bv.x;
    yv.y = (xv.y - mu) * inv * gv.y + bv.y;
    yv.z = (xv.z - mu) * inv * gv.z + bv.z;
    yv.w = (xv.w - mu) * inv * gv.w + bv.w;
    *(float4*)&g_xn[(size_t)row * DD + tid * 4] = yv;
}

// ---------------- tf32 tensor-core GEMM: C = A @ W^T + bias ----------------
// A [8192,1024] rm. W [e,d] rm -> B col-major (k,n) = W[n][k].
// Block tile 128x128, BK=32, 8 warps (warp tile 64x32).
// mode 0/1/2: A=g_xn, C scattered into g_q/g_k/g_v [B,H,T,DK].
// mode 3:     A=g_ao, C = dout [B,T,D], fused (acc+bias)*0.5.
#define GSTR 36
__global__ __launch_bounds__(256) void gemm_tc_kernel(
    const float* __restrict__ W, const float* __restrict__ bias,
    int mode, float* __restrict__ dout) {
    __shared__ float As[128][GSTR];
    __shared__ float Bs[128][GSTR];
    const float* Aptr = (mode < 3) ? g_xn : g_ao;

    int tid  = threadIdx.x;
    int wid  = tid >> 5;
    int lane = tid & 31;
    int g = lane >> 2, t = lane & 3;
    int wm = (wid >> 2) * 64;       // 0 or 64
    int wn = (wid & 3) * 32;        // 0,32,64,96
    int m0 = blockIdx.y * 128;
    int n0 = blockIdx.x * 128;

    float acc[4][4][4];
    #pragma unroll
    for (int i = 0; i < 4; i++)
        #pragma unroll
        for (int j = 0; j < 4; j++)
            #pragma unroll
            for (int e = 0; e < 4; e++) acc[i][j][e] = 0.f;

    for (int k0 = 0; k0 < DD; k0 += 32) {
        __syncthreads();
        // load A,B tiles (128x32 each), convert to tf32 bits at store
        #pragma unroll
        for (int p = 0; p < 4; p++) {
            int slot = tid + p * 256;          // 0..1023
            int row  = slot >> 3;
            int col4 = (slot & 7) * 4;
            float4 av = *(const float4*)&Aptr[(size_t)(m0 + row) * DD + k0 + col4];
            float4 bv = *(const float4*)&W[(size_t)(n0 + row) * DD + k0 + col4];
            float4 at, bt;
            at.x = __uint_as_float(f2tf(av.x)); at.y = __uint_as_float(f2tf(av.y));
            at.z = __uint_as_float(f2tf(av.z)); at.w = __uint_as_float(f2tf(av.w));
            bt.x = __uint_as_float(f2tf(bv.x)); bt.y = __uint_as_float(f2tf(bv.y));
            bt.z = __uint_as_float(f2tf(bv.z)); bt.w = __uint_as_float(f2tf(bv.w));
            *(float4*)&As[row][col4] = at;
            *(float4*)&Bs[row][col4] = bt;
        }
        __syncthreads();

        #pragma unroll
        for (int ks = 0; ks < 4; ks++) {
            int kc = ks * 8;
            unsigned bf[4][2];
            #pragma unroll
            for (int n = 0; n < 4; n++) {
                bf[n][0] = __float_as_uint(Bs[wn + n * 8 + g][kc + t]);
                bf[n][1] = __float_as_uint(Bs[wn + n * 8 + g][kc + t + 4]);
            }
            #pragma unroll
            for (int mI = 0; mI < 4; mI++) {
                int rb = wm + mI * 16;
                unsigned af[4];
                af[0] = __float_as_uint(As[rb + g][kc + t]);
                af[1] = __float_as_uint(As[rb + g + 8][kc + t]);
                af[2] = __float_as_uint(As[rb + g][kc + t + 4]);
                af[3] = __float_as_uint(As[rb + g + 8][kc + t + 4]);
                #pragma unroll
                for (int n = 0; n < 4; n++)
                    mma_tf32(acc[mI][n], af, bf[n], acc[mI][n]);
            }
        }
    }

    // epilogue
    #pragma unroll
    for (int mI = 0; mI < 4; mI++) {
        int r0 = m0 + wm + mI * 16 + g;
        int r1 = r0 + 8;
        #pragma unroll
        for (int n = 0; n < 4; n++) {
            int e = n0 + wn + n * 8 + 2 * t;    // even, pair (e, e+1) same head
            float b0 = bias[e], b1 = bias[e + 1];
            if (mode < 3) {
                float* C = (mode == 0) ? g_q : (mode == 1) ? g_k : g_v;
                int h = e >> 6, dk = e & 63;
                int bi0 = r0 >> 11, t0 = r0 & (TT - 1);
                int bi1 = r1 >> 11, t1 = r1 & (TT - 1);
                float2 v0 = make_float2(acc[mI][n][0] + b0, acc[mI][n][1] + b1);
                float2 v1 = make_float2(acc[mI][n][2] + b0, acc[mI][n][3] + b1);
                *(float2*)&C[((((size_t)bi0 * HH + h) * TT + t0) << 6) + dk] = v0;
                *(float2*)&C[((((size_t)bi1 * HH + h) * TT + t1) << 6) + dk] = v1;
            } else {
                float2 v0 = make_float2((acc[mI][n][0] + b0) * 0.5f,
                                        (acc[mI][n][1] + b1) * 0.5f);
                float2 v1 = make_float2((acc[mI][n][2] + b0) * 0.5f,
                                        (acc[mI][n][3] + b1) * 0.5f);
                *(float2*)&dout[(size_t)r0 * DD + e] = v0;
                *(float2*)&dout[(size_t)r1 * DD + e] = v1;
            }
        }
    }
}

// ---------------- L2 normalize rows of 64 (Q and K) ----------------
__global__ __launch_bounds__(256) void l2norm_kernel() {
    int warp = (blockIdx.x * blockDim.x + threadIdx.x) >> 5;
    int lane = threadIdx.x & 31;
    float* base = (blockIdx.y == 0) ? g_q : g_k;
    float* p = base + (size_t)warp * DKK + lane * 2;
    float2 v = *(float2*)p;
    float ss = v.x * v.x + v.y * v.y;
    #pragma unroll
    for (int o = 16; o > 0; o >>= 1) ss += __shfl_xor_sync(~0u, ss, o);
    float n = sqrtf(ss);
    float inv = 1.0f / fmaxf(n, EPS_NORM_);
    v.x *= inv; v.y *= inv;
    *(float2*)p = v;
}

// ---------------- Flash attention, tf32 tensor cores ----------------
// Block: 64 queries, 4 warps (128 thr). Warp owns 16 q rows.
// Per 64-key tile: S(16x64)=Q.K^T via mma; online softmax in regs;
// P staged through smem (aliased over K tile); O(16x64) += P.V via mma.
#define ASTR 68
__global__ __launch_bounds__(128) void attn_tc_kernel() {
    __shared__ float KsPs[64][ASTR];   // K tile, later aliased as P tile
    __shared__ float Vs[64][ASTR];
    __shared__ float Msf[64];

    int bh = blockIdx.y;
    int bi = bh >> 4;
    int h  = bh & 15;
    int qt = blockIdx.x;               // 64-query tile
    int tid = threadIdx.x;
    int wid = tid >> 5;
    int lane = tid & 31;
    int g = lane >> 2, t = lane & 3;
    int wg = wid * 16;                 // warp's local q-row base

    // Q a-frags resident in registers: 8 k-steps x 4 regs
    unsigned qa[8][4];
    {
        size_t qb0 = ((size_t)(bh * TT + qt * 64 + wg + g)) << 6;
        size_t qb1 = qb0 + (8 << 6);
        #pragma unroll
        for (int ks = 0; ks < 8; ks++) {
            int c = ks * 8 + t;
            qa[ks][0] = f2tf(g_q[qb0 + c]);
            qa[ks][1] = f2tf(g_q[qb1 + c]);
            qa[ks][2] = f2tf(g_q[qb0 + c + 4]);
            qa[ks][3] = f2tf(g_q[qb1 + c + 4]);
        }
    }

    float o_acc[8][4];
    #pragma unroll
    for (int n = 0; n < 8; n++)
        #pragma unroll
        for (int e = 0; e < 4; e++) o_acc[n][e] = 0.f;
    float mrow0 = -1e30f, mrow1 = -1e30f;
    float lrow0 = 0.f, lrow1 = 0.f;

    const unsigned char* mrow = g_cmask + bi * TT;
    const float* kbase = g_k + (((size_t)bh * TT) << 6);
    const float* vbase = g_v + (((size_t)bh * TT) << 6);

    for (int kt = 0; kt < TT / 64; kt++) {
        __syncthreads();   // prior-tile Vs/Ps fully consumed
        // load K,V tiles (64x64 each) with tf32 conversion
        const float* kb = kbase + ((size_t)(kt * 64) << 6);
        const float* vb = vbase + ((size_t)(kt * 64) << 6);
        #pragma unroll
        for (int p = 0; p < 8; p++) {
            int slot = tid + p * 128;       // 0..1023 float4 slots
            int row  = slot >> 4;
            int col4 = (slot & 15) * 4;
            float4 kv = *(const float4*)&kb[(row << 6) + col4];
            float4 vv = *(const float4*)&vb[(row << 6) + col4];
            float4 ktv, vtv;
            ktv.x = __uint_as_float(f2tf(kv.x)); ktv.y = __uint_as_float(f2tf(kv.y));
            ktv.z = __uint_as_float(f2tf(kv.z)); ktv.w = __uint_as_float(f2tf(kv.w));
            vtv.x = __uint_as_float(f2tf(vv.x)); vtv.y = __uint_as_float(f2tf(vv.y));
            vtv.z = __uint_as_float(f2tf(vv.z)); vtv.w = __uint_as_float(f2tf(vv.w));
            *(float4*)&KsPs[row][col4] = ktv;
            *(float4*)&Vs[row][col4]   = vtv;
        }
        if (tid < 64) Msf[tid] = (float)mrow[kt * 64 + tid];
        __syncthreads();

        // ---- S = Q.K^T  (16 x 64 per warp) ----
        float sc[8][4];
        #pragma unroll
        for (int n = 0; n < 8; n++)
            #pragma unroll
            for (int e = 0; e < 4; e++) sc[n][e] = 0.f;
        #pragma unroll
        for (int ks = 0; ks < 8; ks++) {
            int kc = ks * 8;
            #pragma unroll
            for (int n = 0; n < 8; n++) {
                unsigned bf[2];
                bf[0] = __float_as_uint(KsPs[n * 8 + g][kc + t]);
                bf[1] = __float_as_uint(KsPs[n * 8 + g][kc + t + 4]);
                mma_tf32(sc[n], qa[ks], bf, sc[n]);
            }
        }

        // ---- softmax (rows r0 = wg+g, r1 = wg+g+8; cols n*8+2t, +1) ----
        float rmax0 = -1e30f, rmax1 = -1e30f;
        #pragma unroll
        for (int n = 0; n < 8; n++) {
            float mv0 = Msf[n * 8 + 2 * t];
            float mv1 = Msf[n * 8 + 2 * t + 1];
            #pragma unroll
            for (int e = 0; e < 4; e++) {
                float s = sc[n][e] * SCALE_;
                s = fminf(fmaxf(s, -10.f), 10.f);
                float mv = (e & 1) ? mv1 : mv0;
                if (mv != 0.f) s = -10000.f;
                sc[n][e] = s;
            }
            rmax0 = fmaxf(rmax0, fmaxf(sc[n][0], sc[n][1]));
            rmax1 = fmaxf(rmax1, fmaxf(sc[n][2], sc[n][3]));
        }
        rmax0 = fmaxf(rmax0, __shfl_xor_sync(~0u, rmax0, 1));
        rmax0 = fmaxf(rmax0, __shfl_xor_sync(~0u, rmax0, 2));
        rmax1 = fmaxf(rmax1, __shfl_xor_sync(~0u, rmax1, 1));
        rmax1 = fmaxf(rmax1, __shfl_xor_sync(~0u, rmax1, 2));

        float mnew0 = fmaxf(mrow0, rmax0);
        float mnew1 = fmaxf(mrow1, rmax1);
        float corr0 = __expf(mrow0 - mnew0);
        float corr1 = __expf(mrow1 - mnew1);
        mrow0 = mnew0; mrow1 = mnew1;

        float psum0 = 0.f, psum1 = 0.f;
        #pragma unroll
        for (int n = 0; n < 8; n++) {
            sc[n][0] = __expf(sc[n][0] - mnew0);
            sc[n][1] = __expf(sc[n][1] - mnew0);
            sc[n][2] = __expf(sc[n][2] - mnew1);
            sc[n][3] = __expf(sc[n][3] - mnew1);
            psum0 += sc[n][0] + sc[n][1];
            psum1 += sc[n][2] + sc[n][3];
        }
        psum0 += __shfl_xor_sync(~0u, psum0, 1);
        psum0 += __shfl_xor_sync(~0u, psum0, 2);
        psum1 += __shfl_xor_sync(~0u, psum1, 1);
        psum1 += __shfl_xor_sync(~0u, psum1, 2);
        lrow0 = lrow0 * corr0 + psum0;
        lrow1 = lrow1 * corr1 + psum1;
        #pragma unroll
        for (int n = 0; n < 8; n++) {
            o_acc[n][0] *= corr0; o_acc[n][1] *= corr0;
            o_acc[n][2] *= corr1; o_acc[n][3] *= corr1;
        }

        __syncthreads();   // all warps done reading K tile -> safe to alias as P

        // write P (tf32) to smem, rows wg+g / wg+g+8
        #pragma unroll
        for (int n = 0; n < 8; n++) {
            int c = n * 8 + 2 * t;
            float2 p0 = make_float2(__uint_as_float(f2tf(sc[n][0])),
                                    __uint_as_float(f2tf(sc[n][1])));
            float2 p1 = make_float2(__uint_as_float(f2tf(sc[n][2])),
                                    __uint_as_float(f2tf(sc[n][3])));
            *(float2*)&KsPs[wg + g][c]     = p0;
            *(float2*)&KsPs[wg + g + 8][c] = p1;
        }
        __syncwarp();

        // ---- O += P.V  (16 x 64 per warp) ----
        #pragma unroll
        for (int ks = 0; ks < 8; ks++) {
            int kc = ks * 8;
            unsigned pa[4];
            pa[0] = __float_as_uint(KsPs[wg + g][kc + t]);
            pa[1] = __float_as_uint(KsPs[wg + g + 8][kc + t]);
            pa[2] = __float_as_uint(KsPs[wg + g][kc + t + 4]);
            pa[3] = __float_as_uint(KsPs[wg + g + 8][kc + t + 4]);
            #pragma unroll
            for (int n = 0; n < 8; n++) {
                unsigned bf[2];
                bf[0] = __float_as_uint(Vs[kc + t][n * 8 + g]);
                bf[1] = __float_as_uint(Vs[kc + t + 4][n * 8 + g]);
                mma_tf32(o_acc[n], pa, bf, o_acc[n]);
            }
        }
    }

    // ---- epilogue: O /= l, write to g_ao [B,T,D] at cols h*64.. ----
    float inv0 = 1.0f / lrow0;
    float inv1 = 1.0f / lrow1;
    int tq0 = qt * 64 + wg + g;
    int tq1 = tq0 + 8;
    float* ob0 = g_ao + ((size_t)bi * TT + tq0) * DD + h * 64;
    float* ob1 = g_ao + ((size_t)bi * TT + tq1) * DD + h * 64;
    #pragma unroll
    for (int n = 0; n < 8; n++) {
        int c = n * 8 + 2 * t;
        *(float2*)&ob0[c] = make_float2(o_acc[n][0] * inv0, o_acc[n][1] * inv0);
        *(float2*)&ob1[c] = make_float2(o_acc[n][2] * inv1, o_acc[n][3] * inv1);
    }
}

// ---------------- launch ----------------
extern "C" void kernel_launch(void* const* d_in, const int* in_sizes, int n_in,
                              void* d_out, int out_size) {
    const float* x    = (const float*)d_in[0];
    const void*  mask = d_in[1];
    const float* wq = (const float*)d_in[2];
    const float* bq = (const float*)d_in[3];
    const float* wk = (const float*)d_in[4];
    const float* bk = (const float*)d_in[5];
    const float* wv = (const float*)d_in[6];
    const float* bv = (const float*)d_in[7];
    const float* wo = (const float*)d_in[8];
    const float* bo = (const float*)d_in[9];
    const float* ln_g = (const float*)d_in[10];
    const float* ln_b = (const float*)d_in[11];
    float* out = (float*)d_out;

    detect_mask_kernel<<<1, 256>>>((const unsigned char*)mask);
    convert_mask_kernel<<<(BB * TT + 255) / 256, 256>>>(mask);
    ln_kernel<<<BB * TT, 256>>>(x, ln_g, ln_b);

    dim3 ggrid(DD / 128, (BB * TT) / 128);   // (8, 64)
    gemm_tc_kernel<<<ggrid, 256>>>(wq, bq, 0, nullptr);
    gemm_tc_kernel<<<ggrid, 256>>>(wk, bk, 1, nullptr);
    gemm_tc_kernel<<<ggrid, 256>>>(wv, bv, 2, nullptr);

    dim3 l2grid((BB * HH * TT) / 8, 2);
    l2norm_kernel<<<l2grid, 256>>>();

    dim3 agrid(TT / 64, BB * HH);            // (32, 64)
    attn_tc_kernel<<<agrid, 128>>>();

    gemm_tc_kernel<<<ggrid, 256>>>(wo, bo, 3, out);
}

// round 3
// speedup vs baseline: 8.9524x; 1.3506x over previous
#include <cuda_runtime.h>
#include <cstdint>

// Problem constants
#define BB 4
#define TT 2048
#define DD 1024
#define HH 16
#define DKK 64
#define SCALE_ 0.125f
#define EPS_LN_ 1e-5f
#define EPS_NORM_ 1e-8f

// ---------------- scratch ----------------
__device__ float g_xn[BB * TT * DD];
__device__ float g_q[BB * HH * TT * DKK];
__device__ float g_k[BB * HH * TT * DKK];
__device__ float g_v[BB * HH * TT * DKK];
__device__ float g_ao[BB * TT * DD];
__device__ float g_wc[4 * DD * DD];            // tf32-rounded weights q,k,v,o
__device__ unsigned char g_cmask[BB * TT];
__device__ int g_flags[3];

// ---------------- helpers ----------------
__device__ __forceinline__ unsigned f2tf(float x) {
    unsigned r;
    asm("cvt.rna.tf32.f32 %0, %1;" : "=r"(r) : "f"(x));
    return r;
}
__device__ __forceinline__ float f2tff(float x) { return __uint_as_float(f2tf(x)); }

__device__ __forceinline__ void mma_tf32(float* d, const unsigned* a,
                                         const unsigned* b, const float* c) {
    asm volatile(
        "mma.sync.aligned.m16n8k8.row.col.f32.tf32.tf32.f32 "
        "{%0,%1,%2,%3}, {%4,%5,%6,%7}, {%8,%9}, {%10,%11,%12,%13};"
        : "=f"(d[0]), "=f"(d[1]), "=f"(d[2]), "=f"(d[3])
        : "r"(a[0]), "r"(a[1]), "r"(a[2]), "r"(a[3]),
          "r"(b[0]), "r"(b[1]),
          "f"(c[0]), "f"(c[1]), "f"(c[2]), "f"(c[3]));
}
__device__ __forceinline__ void cp_async16(uint32_t saddr, const void* gptr) {
    asm volatile("cp.async.cg.shared.global [%0], [%1], 16;\n" :: "r"(saddr), "l"(gptr));
}
__device__ __forceinline__ void cp_commit() {
    asm volatile("cp.async.commit_group;\n" ::);
}
__device__ __forceinline__ void cp_wait0() {
    asm volatile("cp.async.wait_group 0;\n" ::);
}
__device__ __forceinline__ uint32_t smem_u32(const void* p) {
    return (uint32_t)__cvta_generic_to_shared(p);
}

// ---------------- mask dtype detection / canonicalization ----------------
__global__ void detect_mask_kernel(const unsigned char* __restrict__ m) {
    if (threadIdx.x == 0) { g_flags[0] = 0; g_flags[1] = 0; g_flags[2] = 0; }
    __syncthreads();
    int a = 0, bhi = 0, c = 0;
    for (int i = threadIdx.x; i < BB * TT; i += blockDim.x) {
        unsigned char v = m[i];
        if (v) {
            int r = i & 3;
            if (r == 0) a = 1;
            else if (r == 1) c = 1;
            else bhi = 1;
        }
    }
    if (a)   atomicOr(&g_flags[0], 1);
    if (bhi) atomicOr(&g_flags[1], 1);
    if (c)   atomicOr(&g_flags[2], 1);
}
__global__ void convert_mask_kernel(const void* __restrict__ m) {
    int i = blockIdx.x * blockDim.x + threadIdx.x;
    if (i >= BB * TT) return;
    int A = g_flags[0], Bf = g_flags[1], C = g_flags[2];
    unsigned char out;
    if (A && !Bf && !C)      out = (((const int*)m)[i] != 0);
    else if (!A && Bf)       out = (((const float*)m)[i] != 0.0f);
    else                     out = (((const unsigned char*)m)[i] != 0);
    g_cmask[i] = out;
}

// ---------------- weight conversion (one-shot, tf32 round) ----------------
__global__ __launch_bounds__(256) void wconv_kernel(
    const float* __restrict__ w0, const float* __restrict__ w1,
    const float* __restrict__ w2, const float* __restrict__ w3) {
    const float* src = (blockIdx.y == 0) ? w0 : (blockIdx.y == 1) ? w1
                     : (blockIdx.y == 2) ? w2 : w3;
    float* dst = g_wc + (size_t)blockIdx.y * DD * DD;
    size_t i = ((size_t)blockIdx.x * 256 + threadIdx.x) * 4;
    float4 v = *(const float4*)&src[i];
    v.x = f2tff(v.x); v.y = f2tff(v.y); v.z = f2tff(v.z); v.w = f2tff(v.w);
    *(float4*)&dst[i] = v;
}

// ---------------- LayerNorm (tf32-rounded output) ----------------
__global__ __launch_bounds__(256) void ln_kernel(
    const float* __restrict__ x, const float* __restrict__ g,
    const float* __restrict__ b) {
    __shared__ float red_s[8], red_ss[8];
    int row = blockIdx.x;
    int tid = threadIdx.x;
    const float* xr = x + (size_t)row * DD;
    float4 xv = *(const float4*)&xr[tid * 4];
    float s  = xv.x + xv.y + xv.z + xv.w;
    float ss = xv.x*xv.x + xv.y*xv.y + xv.z*xv.z + xv.w*xv.w;
    #pragma unroll
    for (int o = 16; o > 0; o >>= 1) {
        s  += __shfl_xor_sync(~0u, s, o);
        ss += __shfl_xor_sync(~0u, ss, o);
    }
    int warp = tid >> 5, lane = tid & 31;
    if (lane == 0) { red_s[warp] = s; red_ss[warp] = ss; }
    __syncthreads();
    if (warp == 0) {
        s  = (lane < 8) ? red_s[lane]  : 0.f;
        ss = (lane < 8) ? red_ss[lane] : 0.f;
        #pragma unroll
        for (int o = 4; o > 0; o >>= 1) {
            s  += __shfl_xor_sync(~0u, s, o);
            ss += __shfl_xor_sync(~0u, ss, o);
        }
        if (lane == 0) { red_s[0] = s; red_ss[0] = ss; }
    }
    __syncthreads();
    float mu  = red_s[0] * (1.0f / DD);
    float var = red_ss[0] * (1.0f / DD) - mu * mu;
    float inv = rsqrtf(var + EPS_LN_);
    float4 gv = *(const float4*)&g[tid * 4];
    float4 bv = *(const float4*)&b[tid * 4];
    float4 yv;
    yv.x = f2tff((xv.x - mu) * inv * gv.x + bv.x);
    yv.y = f2tff((xv.y - mu) * inv * gv.y + bv.y);
    yv.z = f2tff((xv.z - mu) * inv * gv.z + bv.z);
    yv.w = f2tff((xv.w - mu) * inv * gv.w + bv.w);
    *(float4*)&g_xn[(size_t)row * DD + tid * 4] = yv;
}

// ---------------- tf32 GEMM, cp.async double-buffered ----------------
// mode_base 0: fused QKV (mode = blockIdx.z); mode_base 3: O-projection.
#define GSTR 36
#define GTILE (128 * GSTR)
__global__ __launch_bounds__(256) void gemm_tc_kernel(
    const float* __restrict__ b0, const float* __restrict__ b1,
    const float* __restrict__ b2, int mode_base, float* __restrict__ dout) {
    extern __shared__ float gsm[];   // A0 A1 B0 B1, each 128*GSTR floats
    int mode = (mode_base == 3) ? 3 : (int)blockIdx.z;
    const float* W = g_wc + (size_t)mode * DD * DD;
    const float* bias = (mode == 1) ? b1 : (mode == 2) ? b2 : b0;
    const float* Aptr = (mode < 3) ? g_xn : g_ao;

    int tid  = threadIdx.x;
    int wid  = tid >> 5;
    int lane = tid & 31;
    int g = lane >> 2, t = lane & 3;
    int wm = (wid >> 2) * 64;
    int wn = (wid & 3) * 32;
    int m0 = blockIdx.y * 128;
    int n0 = blockIdx.x * 128;

    uint32_t sbase = smem_u32(gsm);
    int arow = tid >> 1;
    int ak4  = (tid & 1) * 4;   // unused alt layout; keep slot mapping below

    float acc[4][4][4];
    #pragma unroll
    for (int i = 0; i < 4; i++)
        #pragma unroll
        for (int j = 0; j < 4; j++)
            #pragma unroll
            for (int e = 0; e < 4; e++) acc[i][j][e] = 0.f;

    // stage loader: 4 float4 per thread for A and B each
    auto load_stage = [&](int k0, int st) {
        #pragma unroll
        for (int p = 0; p < 4; p++) {
            int slot = tid + p * 256;
            int row  = slot >> 3;
            int col4 = (slot & 7) * 4;
            const float* ga = &Aptr[(size_t)(m0 + row) * DD + k0 + col4];
            const float* gb = &W[(size_t)(n0 + row) * DD + k0 + col4];
            cp_async16(sbase + (uint32_t)((st * GTILE + row * GSTR + col4) * 4), ga);
            cp_async16(sbase + (uint32_t)(((2 + st) * GTILE + row * GSTR + col4) * 4), gb);
        }
        cp_commit();
    };

    load_stage(0, 0);
    for (int it = 0; it < DD / 32; it++) {
        int cur = it & 1;
        cp_wait0();
        __syncthreads();
        if (it < DD / 32 - 1) load_stage((it + 1) * 32, cur ^ 1);
        const float* As = gsm + cur * GTILE;
        const float* Bs = gsm + (2 + cur) * GTILE;
        #pragma unroll
        for (int ks = 0; ks < 4; ks++) {
            int kc = ks * 8;
            unsigned bf[4][2];
            #pragma unroll
            for (int n = 0; n < 4; n++) {
                bf[n][0] = __float_as_uint(Bs[(wn + n * 8 + g) * GSTR + kc + t]);
                bf[n][1] = __float_as_uint(Bs[(wn + n * 8 + g) * GSTR + kc + t + 4]);
            }
            #pragma unroll
            for (int mI = 0; mI < 4; mI++) {
                int rb = wm + mI * 16;
                unsigned af[4];
                af[0] = __float_as_uint(As[(rb + g) * GSTR + kc + t]);
                af[1] = __float_as_uint(As[(rb + g + 8) * GSTR + kc + t]);
                af[2] = __float_as_uint(As[(rb + g) * GSTR + kc + t + 4]);
                af[3] = __float_as_uint(As[(rb + g + 8) * GSTR + kc + t + 4]);
                #pragma unroll
                for (int n = 0; n < 4; n++)
                    mma_tf32(acc[mI][n], af, bf[n], acc[mI][n]);
            }
        }
    }

    #pragma unroll
    for (int mI = 0; mI < 4; mI++) {
        int r0 = m0 + wm + mI * 16 + g;
        int r1 = r0 + 8;
        #pragma unroll
        for (int n = 0; n < 4; n++) {
            int e = n0 + wn + n * 8 + 2 * t;
            float bb0 = bias[e], bb1 = bias[e + 1];
            if (mode < 3) {
                float* C = (mode == 0) ? g_q : (mode == 1) ? g_k : g_v;
                int h = e >> 6, dk = e & 63;
                int bi0 = r0 >> 11, t0 = r0 & (TT - 1);
                int bi1 = r1 >> 11, t1 = r1 & (TT - 1);
                float2 v0 = make_float2(acc[mI][n][0] + bb0, acc[mI][n][1] + bb1);
                float2 v1 = make_float2(acc[mI][n][2] + bb0, acc[mI][n][3] + bb1);
                if (mode == 2) {   // V consumed directly by mma: round now
                    v0.x = f2tff(v0.x); v0.y = f2tff(v0.y);
                    v1.x = f2tff(v1.x); v1.y = f2tff(v1.y);
                }
                *(float2*)&C[((((size_t)bi0 * HH + h) * TT + t0) << 6) + dk] = v0;
                *(float2*)&C[((((size_t)bi1 * HH + h) * TT + t1) << 6) + dk] = v1;
            } else {
                float2 v0 = make_float2((acc[mI][n][0] + bb0) * 0.5f,
                                        (acc[mI][n][1] + bb1) * 0.5f);
                float2 v1 = make_float2((acc[mI][n][2] + bb0) * 0.5f,
                                        (acc[mI][n][3] + bb1) * 0.5f);
                *(float2*)&dout[(size_t)r0 * DD + e] = v0;
                *(float2*)&dout[(size_t)r1 * DD + e] = v1;
            }
        }
    }
}

// ---------------- L2 normalize (tf32-rounded output) ----------------
__global__ __launch_bounds__(256) void l2norm_kernel() {
    int warp = (blockIdx.x * blockDim.x + threadIdx.x) >> 5;
    int lane = threadIdx.x & 31;
    float* base = (blockIdx.y == 0) ? g_q : g_k;
    float* p = base + (size_t)warp * DKK + lane * 2;
    float2 v = *(float2*)p;
    float ss = v.x * v.x + v.y * v.y;
    #pragma unroll
    for (int o = 16; o > 0; o >>= 1) ss += __shfl_xor_sync(~0u, ss, o);
    float n = sqrtf(ss);
    float inv = 1.0f / fmaxf(n, EPS_NORM_);
    v.x = f2tff(v.x * inv); v.y = f2tff(v.y * inv);
    *(float2*)p = v;
}

// ---------------- Flash attention: static softmax + cp.async ----------------
// |q.k|*SCALE <= 0.125 (L2-normed), so clip & running-max are provably no-ops:
// softmax(s - max) == exp(s)/sum(exp(s)); masked -> exp(-10000-max) == 0 -> w=0.
#define ASTR 68
#define ATILE (64 * ASTR)
#define ASMEM (4 * ATILE * 4 + TT)   // bytes: K0 K1 V0 V1 + mask row
__global__ __launch_bounds__(128) void attn_tc_kernel() {
    extern __shared__ float asm_[];
    unsigned char* Msk = (unsigned char*)(asm_ + 4 * ATILE);

    int bh = blockIdx.y;
    int bi = bh >> 4;
    int h  = bh & 15;
    int qt = blockIdx.x;
    int tid = threadIdx.x;
    int wid = tid >> 5;
    int lane = tid & 31;
    int g = lane >> 2, t = lane & 3;
    int wg = wid * 16;
    uint32_t sbase = smem_u32(asm_);

    // preload full mask row (2048 B)
    ((uint4*)Msk)[tid] = ((const uint4*)(g_cmask + bi * TT))[tid];

    // resident Q fragments (already tf32-rounded by l2norm)
    unsigned qa[8][4];
    {
        size_t qb0 = ((size_t)(bh * TT + qt * 64 + wg + g)) << 6;
        size_t qb1 = qb0 + (8 << 6);
        #pragma unroll
        for (int ks = 0; ks < 8; ks++) {
            int c = ks * 8 + t;
            qa[ks][0] = __float_as_uint(g_q[qb0 + c]);
            qa[ks][1] = __float_as_uint(g_q[qb1 + c]);
            qa[ks][2] = __float_as_uint(g_q[qb0 + c + 4]);
            qa[ks][3] = __float_as_uint(g_q[qb1 + c + 4]);
        }
    }

    float o_acc[8][4];
    #pragma unroll
    for (int n = 0; n < 8; n++)
        #pragma unroll
        for (int e = 0; e < 4; e++) o_acc[n][e] = 0.f;
    float psum0 = 0.f, psum1 = 0.f;

    const float* kbase = g_k + (((size_t)bh * TT) << 6);
    const float* vbase = g_v + (((size_t)bh * TT) << 6);

    auto load_kv = [&](int kt, int st) {
        const float* kb = kbase + ((size_t)(kt * 64) << 6);
        const float* vb = vbase + ((size_t)(kt * 64) << 6);
        #pragma unroll
        for (int p = 0; p < 8; p++) {
            int slot = tid + p * 128;
            int row  = slot >> 4;
            int col4 = (slot & 15) * 4;
            cp_async16(sbase + (uint32_t)((st * ATILE + row * ASTR + col4) * 4),
                       &kb[(row << 6) + col4]);
            cp_async16(sbase + (uint32_t)(((2 + st) * ATILE + row * ASTR + col4) * 4),
                       &vb[(row << 6) + col4]);
        }
        cp_commit();
    };

    load_kv(0, 0);
    for (int kt = 0; kt < TT / 64; kt++) {
        int cur = kt & 1;
        cp_wait0();
        __syncthreads();                 // tile kt arrived; prev PV done; mask visible
        if (kt < TT / 64 - 1) load_kv(kt + 1, cur ^ 1);

        float* Ks = asm_ + cur * ATILE;
        float* Vs = asm_ + (2 + cur) * ATILE;

        // S = Q.K^T
        float sc[8][4];
        #pragma unroll
        for (int n = 0; n < 8; n++)
            #pragma unroll
            for (int e = 0; e < 4; e++) sc[n][e] = 0.f;
        #pragma unroll
        for (int ks = 0; ks < 8; ks++) {
            int kc = ks * 8;
            #pragma unroll
            for (int n = 0; n < 8; n++) {
                unsigned bf[2];
                bf[0] = __float_as_uint(Ks[(n * 8 + g) * ASTR + kc + t]);
                bf[1] = __float_as_uint(Ks[(n * 8 + g) * ASTR + kc + t + 4]);
                mma_tf32(sc[n], qa[ks], bf, sc[n]);
            }
        }

        // static softmax weights
        const unsigned char* mrow = Msk + kt * 64;
        #pragma unroll
        for (int n = 0; n < 8; n++) {
            bool mk0 = mrow[n * 8 + 2 * t] != 0;
            bool mk1 = mrow[n * 8 + 2 * t + 1] != 0;
            sc[n][0] = mk0 ? 0.f : __expf(sc[n][0] * SCALE_);
            sc[n][1] = mk1 ? 0.f : __expf(sc[n][1] * SCALE_);
            sc[n][2] = mk0 ? 0.f : __expf(sc[n][2] * SCALE_);
            sc[n][3] = mk1 ? 0.f : __expf(sc[n][3] * SCALE_);
            psum0 += sc[n][0] + sc[n][1];
            psum1 += sc[n][2] + sc[n][3];
        }

        __syncthreads();                 // all warps done reading K[cur]
        // P (tf32-rounded) -> alias over K[cur]
        #pragma unroll
        for (int n = 0; n < 8; n++) {
            int c = n * 8 + 2 * t;
            *(float2*)&Ks[(wg + g) * ASTR + c] =
                make_float2(f2tff(sc[n][0]), f2tff(sc[n][1]));
            *(float2*)&Ks[(wg + g + 8) * ASTR + c] =
                make_float2(f2tff(sc[n][2]), f2tff(sc[n][3]));
        }
        __syncwarp();

        // O += P.V
        #pragma unroll
        for (int ks = 0; ks < 8; ks++) {
            int kc = ks * 8;
            unsigned pa[4];
            pa[0] = __float_as_uint(Ks[(wg + g) * ASTR + kc + t]);
            pa[1] = __float_as_uint(Ks[(wg + g + 8) * ASTR + kc + t]);
            pa[2] = __float_as_uint(Ks[(wg + g) * ASTR + kc + t + 4]);
            pa[3] = __float_as_uint(Ks[(wg + g + 8) * ASTR + kc + t + 4]);
            #pragma unroll
            for (int n = 0; n < 8; n++) {
                unsigned bf[2];
                bf[0] = __float_as_uint(Vs[(kc + t) * ASTR + n * 8 + g]);
                bf[1] = __float_as_uint(Vs[(kc + t + 4) * ASTR + n * 8 + g]);
                mma_tf32(o_acc[n], pa, bf, o_acc[n]);
            }
        }
    }

    // reduce row sums across the 4 lanes sharing a row, then store
    psum0 += __shfl_xor_sync(~0u, psum0, 1);
    psum0 += __shfl_xor_sync(~0u, psum0, 2);
    psum1 += __shfl_xor_sync(~0u, psum1, 1);
    psum1 += __shfl_xor_sync(~0u, psum1, 2);
    float inv0 = 1.0f / psum0;
    float inv1 = 1.0f / psum1;
    int tq0 = qt * 64 + wg + g;
    int tq1 = tq0 + 8;
    float* ob0 = g_ao + ((size_t)bi * TT + tq0) * DD + h * 64;
    float* ob1 = g_ao + ((size_t)bi * TT + tq1) * DD + h * 64;
    #pragma unroll
    for (int n = 0; n < 8; n++) {
        int c = n * 8 + 2 * t;
        *(float2*)&ob0[c] = make_float2(f2tff(o_acc[n][0] * inv0),
                                        f2tff(o_acc[n][1] * inv0));
        *(float2*)&ob1[c] = make_float2(f2tff(o_acc[n][2] * inv1),
                                        f2tff(o_acc[n][3] * inv1));
    }
}

// ---------------- launch ----------------
extern "C" void kernel_launch(void* const* d_in, const int* in_sizes, int n_in,
                              void* d_out, int out_size) {
    const float* x    = (const float*)d_in[0];
    const void*  mask = d_in[1];
    const float* wq = (const float*)d_in[2];
    const float* bq = (const float*)d_in[3];
    const float* wk = (const float*)d_in[4];
    const float* bk = (const float*)d_in[5];
    const float* wv = (const float*)d_in[6];
    const float* bv = (const float*)d_in[7];
    const float* wo = (const float*)d_in[8];
    const float* bo = (const float*)d_in[9];
    const float* ln_g = (const float*)d_in[10];
    const float* ln_b = (const float*)d_in[11];
    float* out = (float*)d_out;

    const int gemm_smem = 4 * GTILE * 4;       // 73728 B
    const int attn_smem = ASMEM;               // 71680 B
    cudaFuncSetAttribute(gemm_tc_kernel,
        cudaFuncAttributeMaxDynamicSharedMemorySize, gemm_smem);
    cudaFuncSetAttribute(attn_tc_kernel,
        cudaFuncAttributeMaxDynamicSharedMemorySize, attn_smem);

    detect_mask_kernel<<<1, 256>>>((const unsigned char*)mask);
    convert_mask_kernel<<<(BB * TT + 255) / 256, 256>>>(mask);
    wconv_kernel<<<dim3(DD * DD / 1024, 4), 256>>>(wq, wk, wv, wo);
    ln_kernel<<<BB * TT, 256>>>(x, ln_g, ln_b);

    dim3 qkv_grid(DD / 128, (BB * TT) / 128, 3);
    gemm_tc_kernel<<<qkv_grid, 256, gemm_smem>>>(bq, bk, bv, 0, nullptr);

    dim3 l2grid((BB * HH * TT) / 8, 2);
    l2norm_kernel<<<l2grid, 256>>>();

    dim3 agrid(TT / 64, BB * HH);
    attn_tc_kernel<<<agrid, 128, attn_smem>>>();

    dim3 ogrid(DD / 128, (BB * TT) / 128, 1);
    gemm_tc_kernel<<<ogrid, 256, gemm_smem>>>(bo, nullptr, nullptr, 3, out);
}